// round 3
// baseline (speedup 1.0000x reference)
#include <cuda_runtime.h>

#define THREADS 384
#define NB      4
#define GRIDB   128
#define T_LEN   1000

typedef unsigned long long ull;

__device__ __forceinline__ ull fma2(ull a, ull b, ull c) {
    ull d;
    asm("fma.rn.f32x2 %0, %1, %2, %3;" : "=l"(d) : "l"(a), "l"(b), "l"(c));
    return d;
}
__device__ __forceinline__ float hadd(ull a) {
    return __uint_as_float((unsigned)a) + __uint_as_float((unsigned)(a >> 32));
}
__device__ __forceinline__ float sigf(float x) {
    return __fdividef(1.0f, 1.0f + __expf(-x));
}
__device__ __forceinline__ float tanh_(float x) {
    return 1.0f - __fdividef(2.0f, 1.0f + __expf(2.0f * x));
}

extern "C" __global__ void __launch_bounds__(THREADS, 1)
audiolstm_kernel(const float* __restrict__ x,
                 const float* __restrict__ w_ih1, const float* __restrict__ w_hh1,
                 const float* __restrict__ b_ih1, const float* __restrict__ b_hh1,
                 const float* __restrict__ w_ih2, const float* __restrict__ w_hh2,
                 const float* __restrict__ b_ih2, const float* __restrict__ b_hh2,
                 const float* __restrict__ w_fc1, const float* __restrict__ b_fc1,
                 const float* __restrict__ w_fc2, const float* __restrict__ b_fc2,
                 float* __restrict__ out)
{
    // v layout per batch: v1 = [x(26) | h1(64) | pad(6)], v2 = [h1(64) | h2(32) | pad(4)]
    __shared__ __align__(16) float v1s[NB * 96];
    __shared__ __align__(16) float v2s[NB * 96];
    __shared__ float g1s[NB * 256];
    __shared__ float g2s[NB * 128];
    __shared__ float xss[2 * 8 * 104];   // double-buffered x staging
    __shared__ float fcs[64];

    const int tid = threadIdx.x;
    const int b0  = blockIdx.x * NB;

    // ---------- load this thread's gate-row weights into registers ----------
    float wf[96];
    #pragma unroll
    for (int k = 0; k < 96; ++k) wf[k] = 0.f;
    float bias;
    if (tid < 256) {                       // LSTM1 row tid: [w_ih1 row | w_hh1 row]
        #pragma unroll
        for (int k = 0; k < 26; ++k) wf[k] = w_ih1[tid * 26 + k];
        #pragma unroll
        for (int k = 0; k < 64; ++k) wf[26 + k] = w_hh1[tid * 64 + k];
        bias = b_ih1[tid] + b_hh1[tid];
    } else {                               // LSTM2 row j: [w_ih2 row | w_hh2 row]
        const int j = tid - 256;
        #pragma unroll
        for (int k = 0; k < 64; ++k) wf[k] = w_ih2[j * 64 + k];
        #pragma unroll
        for (int k = 0; k < 32; ++k) wf[64 + k] = w_hh2[j * 32 + k];
        bias = b_ih2[j] + b_hh2[j];
    }
    ull W[48];
    #pragma unroll
    for (int i = 0; i < 48; ++i)
        W[i] = (ull)__float_as_uint(wf[2 * i]) |
               ((ull)__float_as_uint(wf[2 * i + 1]) << 32);
    const ull biasp = (ull)__float_as_uint(bias);

    // ---------- init state vectors ----------
    for (int e = tid; e < NB * 96; e += THREADS) { v1s[e] = 0.f; v2s[e] = 0.f; }

    // ---------- x stager setup (tid < 104): thread = (batch xb_, feature xi_) ----------
    const int  xb_ = tid / 26, xi_ = tid - xb_ * 26;
    const bool xthr = tid < 104;
    const float* xg = xthr ? (x + ((size_t)(b0 + xb_) * 26 + xi_) * T_LEN) : x;
    float4 xa = make_float4(0.f, 0.f, 0.f, 0.f), xb2 = xa;
    if (xthr) {
        xa  = *(const float4*)(xg);
        xb2 = *(const float4*)(xg + 4);
        // stage chunk 0 into buffer 0
        xss[0 * 104 + tid] = xa.x;  xss[1 * 104 + tid] = xa.y;
        xss[2 * 104 + tid] = xa.z;  xss[3 * 104 + tid] = xa.w;
        xss[4 * 104 + tid] = xb2.x; xss[5 * 104 + tid] = xb2.y;
        xss[6 * 104 + tid] = xb2.z; xss[7 * 104 + tid] = xb2.w;
        v1s[xb_ * 96 + xi_] = xa.x;          // x(0)
        // prefetch chunk 1
        xa  = *(const float4*)(xg + 8);
        xb2 = *(const float4*)(xg + 12);
    }

    // role constants
    const float* vb      = (tid < 256) ? v1s : v2s;
    float*       gout    = (tid < 256) ? (g1s + tid) : (g2s + (tid - 256));
    const int    gstride = (tid < 256) ? 256 : 128;
    const int    u1b = tid >> 6,          u1n = tid & 63;          // update1 (tid<256)
    const int    u2b = (tid - 256) >> 5,  u2n = (tid - 256) & 31;  // update2 (tid>=256)

    float c1 = 0.f, c2 = 0.f;
    __syncthreads();

    // ---------- main loop: 1001 iterations.
    // iter t: phase A computes gates1(t) [warps 0-7] and gates2(t-1) [warps 8-11];
    //         phase B applies both state updates. t=1000 only finishes LSTM2.
    #pragma unroll 1
    for (int t = 0; t <= T_LEN; ++t) {
        // ===== phase A: gate GEMV, weights in registers, v broadcast from smem =====
        ull a0 = biasp, a1 = biasp, a2 = biasp, a3 = biasp;
        #pragma unroll
        for (int q = 0; q < 24; ++q) {
            ulonglong2 v;
            v = *(const ulonglong2*)(vb + 0 * 96 + q * 4);
            a0 = fma2(W[2 * q], v.x, a0); a0 = fma2(W[2 * q + 1], v.y, a0);
            v = *(const ulonglong2*)(vb + 1 * 96 + q * 4);
            a1 = fma2(W[2 * q], v.x, a1); a1 = fma2(W[2 * q + 1], v.y, a1);
            v = *(const ulonglong2*)(vb + 2 * 96 + q * 4);
            a2 = fma2(W[2 * q], v.x, a2); a2 = fma2(W[2 * q + 1], v.y, a2);
            v = *(const ulonglong2*)(vb + 3 * 96 + q * 4);
            a3 = fma2(W[2 * q], v.x, a3); a3 = fma2(W[2 * q + 1], v.y, a3);
        }
        gout[0 * gstride] = hadd(a0);
        gout[1 * gstride] = hadd(a1);
        gout[2 * gstride] = hadd(a2);
        gout[3 * gstride] = hadd(a3);
        __syncthreads();                                   // gates ready

        // ===== phase B: state updates + x staging =====
        if (tid < 256) {
            // LSTM1 update for (u1b, u1n): h1(t), c1(t)
            const float gi = g1s[u1b * 256 +       u1n];
            const float gf = g1s[u1b * 256 +  64 + u1n];
            const float gg = g1s[u1b * 256 + 128 + u1n];
            const float go = g1s[u1b * 256 + 192 + u1n];
            const float ii = sigf(gi), ff = sigf(gf);
            const float g  = tanh_(gg), oo = sigf(go);
            c1 = ff * c1 + ii * g;
            const float h = oo * tanh_(c1);
            v1s[u1b * 96 + 26 + u1n] = h;     // LSTM1 recurrence input
            v2s[u1b * 96 +      u1n] = h;     // LSTM2 input
        } else if (t > 0) {
            // LSTM2 update for step t-1
            const float gi = g2s[u2b * 128 +      u2n];
            const float gf = g2s[u2b * 128 + 32 + u2n];
            const float gg = g2s[u2b * 128 + 64 + u2n];
            const float go = g2s[u2b * 128 + 96 + u2n];
            const float ii = sigf(gi), ff = sigf(gf);
            const float g  = tanh_(gg), oo = sigf(go);
            c2 = ff * c2 + ii * g;
            v2s[u2b * 96 + 64 + u2n] = oo * tanh_(c2);
        }
        if (xthr) {
            const int idx = t + 1;
            if (idx < T_LEN)
                v1s[xb_ * 96 + xi_] = xss[(((idx >> 3) & 1) * 8 + (idx & 7)) * 104 + tid];
            if ((t & 7) == 0) {
                const int cn = (t >> 3) + 1;           // chunk already in registers
                if (cn < 125) {
                    float* d = &xss[((cn & 1) * 8) * 104 + tid];
                    d[0 * 104] = xa.x;  d[1 * 104] = xa.y;
                    d[2 * 104] = xa.z;  d[3 * 104] = xa.w;
                    d[4 * 104] = xb2.x; d[5 * 104] = xb2.y;
                    d[6 * 104] = xb2.z; d[7 * 104] = xb2.w;
                    if (cn + 1 < 125) {
                        xa  = *(const float4*)(xg + (size_t)(cn + 1) * 8);
                        xb2 = *(const float4*)(xg + (size_t)(cn + 1) * 8 + 4);
                    }
                }
            }
        }
        __syncthreads();                                   // v ready for next iter
    }

    // ---------- FC head on final h2 = v2s[b][64..95] ----------
    if (tid < 64) {
        const int b = tid >> 4, f = tid & 15;
        float a = __ldg(b_fc1 + f);
        #pragma unroll
        for (int k = 0; k < 32; ++k)
            a += __ldg(w_fc1 + f * 32 + k) * v2s[b * 96 + 64 + k];
        fcs[b * 16 + f] = fmaxf(a, 0.f);
    }
    __syncthreads();
    if (tid < 40) {
        const int b = tid / 10, o = tid - b * 10;
        float a = __ldg(b_fc2 + o);
        #pragma unroll
        for (int k = 0; k < 16; ++k)
            a += __ldg(w_fc2 + o * 16 + k) * fcs[b * 16 + k];
        out[(b0 + b) * 10 + o] = a;
    }
}

extern "C" void kernel_launch(void* const* d_in, const int* in_sizes, int n_in,
                              void* d_out, int out_size) {
    (void)in_sizes; (void)n_in; (void)out_size;
    audiolstm_kernel<<<GRIDB, THREADS>>>(
        (const float*)d_in[0],
        (const float*)d_in[1], (const float*)d_in[2],
        (const float*)d_in[3], (const float*)d_in[4],
        (const float*)d_in[5], (const float*)d_in[6],
        (const float*)d_in[7], (const float*)d_in[8],
        (const float*)d_in[9], (const float*)d_in[10],
        (const float*)d_in[11], (const float*)d_in[12],
        (float*)d_out);
}